// round 11
// baseline (speedup 1.0000x reference)
#include <cuda_runtime.h>

// ---------------------------------------------------------------------------
// MSGMS loss, 4-scale pyramid — fully fused, 3 launches.
//  gms0_k   : scale-0 GMS tiles compute grayscale FROM RGB in stage A (no L0
//             gray round-trip) and emit the pooled L1 (256^2) plane.
//  gms123_k : scales 1-3 in one launch; scale 2 pools L1 2x2 on the fly,
//             scale 3 pools 4x4 (avg-of-avg4, matching reference rounding).
//  finalize_k: fixed-order deterministic sum of per-block partials.
// ---------------------------------------------------------------------------

#define C_GMS 0.0026f

static constexpr int NB   = 16;
static constexpr int HW0  = 512 * 512;
static constexpr int L1HW = 256 * 256;

static constexpr int N0 = 16 * 16 * NB;   // 4096 tiles @512
static constexpr int N1 = 8 * 8 * NB;     // 1024 @256
static constexpr int N2 = 4 * 4 * NB;     // 256  @128
static constexpr int N3 = 2 * 2 * NB;     // 64   @64
static constexpr int NBLK  = N0 + N1 + N2 + N3;   // 5440
static constexpr int N123  = N1 + N2 + N3;        // 1344

__device__ float  g_l1[2][NB * L1HW];   // only surviving intermediate (8.4 MB)
__device__ double g_partial[NBLK];

// ---------------------------------------------------------------------------
struct Smem {
    float g[2][36][48];     // gray tile: row r = gray row OY-1+r, col cc = OX-4+cc
    float med[2][34][40];   // median-of-9 tile
    float wsum[8];
};

__device__ __forceinline__ float med3f(float a, float b, float c) {
    return fmaxf(fminf(a, b), fminf(fmaxf(a, b), c));
}
__device__ __forceinline__ void sort3f(float& a, float& b, float& c) {
    float t;
    t = fminf(a, b); b = fmaxf(a, b); a = t;
    t = fminf(b, c); c = fmaxf(b, c); b = t;
    t = fminf(a, b); b = fmaxf(a, b); a = t;
}

// P=0: gray from RGB (scale 0, also emits L1). P=1: read L1. P=2/4: pool L1.
template <int H, int W, int LOGT, int P>
__device__ __forceinline__ void gms_tile(Smem& sm, int local, int gbid,
                                         const float* __restrict__ I0,
                                         const float* __restrict__ I1) {
    constexpr int T = 1 << LOGT;
    const int bx = local & (T - 1);
    const int by = (local >> LOGT) & (T - 1);
    const int b  = local >> (2 * LOGT);
    const int OX = bx * 32;
    const int OY = by * 32;
    const int tid = threadIdx.x;
    const float inv3 = 1.0f / 3.0f;

    const bool interior = (OX >= 4) && (OX + 36 <= W) && (OY >= 1) && (OY + 35 <= H);

    // ---- Stage A: gray tile via per-quad loads (2 img x 36 rows x 12 quads) ----
    for (int i = tid; i < 864; i += 256) {
        int img = (i >= 432);
        int rem = i - img * 432;
        int r   = rem / 12;
        int k   = rem - 12 * r;
        int gy  = OY - 1 + r;
        int gc  = OX - 4 + 4 * k;
        float vv[4] = {0.f, 0.f, 0.f, 0.f};
        if ((unsigned)gy < (unsigned)H) {
            bool vec = (gc >= 0) && (gc + 4 <= W);
            if constexpr (P == 0) {
                const float* s = (img ? I1 : I0) + (size_t)b * 3 * HW0 + (size_t)gy * 512;
                if (vec) {
                    float4 c0 = *(const float4*)(s + gc);
                    float4 c1 = *(const float4*)(s + gc + HW0);
                    float4 c2 = *(const float4*)(s + gc + 2 * HW0);
                    vv[0] = (c0.x + c1.x + c2.x) * inv3;
                    vv[1] = (c0.y + c1.y + c2.y) * inv3;
                    vv[2] = (c0.z + c1.z + c2.z) * inv3;
                    vv[3] = (c0.w + c1.w + c2.w) * inv3;
                } else {
#pragma unroll
                    for (int j = 0; j < 4; j++) {
                        int x = gc + j;
                        if ((unsigned)x < 512u)
                            vv[j] = (s[x] + s[x + HW0] + s[x + 2 * HW0]) * inv3;
                    }
                }
            } else if constexpr (P == 1) {
                const float* s = &g_l1[img][(size_t)b * L1HW] + (size_t)gy * 256;
                if (vec) {
                    *(float4*)vv = *(const float4*)(s + gc);
                } else {
#pragma unroll
                    for (int j = 0; j < 4; j++) {
                        int x = gc + j;
                        if ((unsigned)x < (unsigned)W) vv[j] = s[x];
                    }
                }
            } else if constexpr (P == 2) {
                const float* s = &g_l1[img][(size_t)b * L1HW] + (size_t)(2 * gy) * 256;
                if (vec) {
                    float4 u0 = *(const float4*)(s + 2 * gc);
                    float4 u1 = *(const float4*)(s + 2 * gc + 4);
                    float4 w0 = *(const float4*)(s + 256 + 2 * gc);
                    float4 w1 = *(const float4*)(s + 256 + 2 * gc + 4);
                    vv[0] = (u0.x + u0.y + w0.x + w0.y) * 0.25f;
                    vv[1] = (u0.z + u0.w + w0.z + w0.w) * 0.25f;
                    vv[2] = (u1.x + u1.y + w1.x + w1.y) * 0.25f;
                    vv[3] = (u1.z + u1.w + w1.z + w1.w) * 0.25f;
                } else {
#pragma unroll
                    for (int j = 0; j < 4; j++) {
                        int x = gc + j;
                        if ((unsigned)x < (unsigned)W) {
                            const float* q = s + 2 * x;
                            vv[j] = (q[0] + q[1] + q[256] + q[257]) * 0.25f;
                        }
                    }
                }
            } else {   // P == 4: L3 = avgpool(avgpool(L1)), reference association
                const float* s = &g_l1[img][(size_t)b * L1HW] + (size_t)(4 * gy) * 256;
#pragma unroll
                for (int j = 0; j < 4; j++) {
                    int x = gc + j;
                    if ((unsigned)x < (unsigned)W) {
                        float a4 = 0.f;
#pragma unroll
                        for (int sy = 0; sy < 2; sy++)
#pragma unroll
                        for (int sx = 0; sx < 2; sx++) {
                            const float* q = s + (size_t)(2 * sy) * 256 + 2 * (2 * x + sx);
                            a4 += (q[0] + q[1] + q[256] + q[257]) * 0.25f;
                        }
                        vv[j] = a4 * 0.25f;
                    }
                }
            }
        }
        *(float4*)&sm.g[img][r][4 * k] = *(float4*)vv;
    }
    __syncthreads();

    // ---- L1 emit (scale 0 only): pooled 16x16 block, 4 LDS.128 -> 1 STG.128 ----
    if constexpr (P == 0) {
        for (int i = tid; i < 128; i += 256) {   // 2 img x 16 rows x 4 quads
            int img = (i >= 64);
            int rem = i - img * 64;
            int r   = rem >> 2;
            int c4  = rem & 3;
            int cb  = 4 + 8 * c4;                // sm col of gray x = OX + 8*c4
            float4 u0 = *(const float4*)&sm.g[img][2 * r + 1][cb];
            float4 u1 = *(const float4*)&sm.g[img][2 * r + 1][cb + 4];
            float4 w0 = *(const float4*)&sm.g[img][2 * r + 2][cb];
            float4 w1 = *(const float4*)&sm.g[img][2 * r + 2][cb + 4];
            float4 o = { (u0.x + u0.y + w0.x + w0.y) * 0.25f,
                         (u0.z + u0.w + w0.z + w0.w) * 0.25f,
                         (u1.x + u1.y + w1.x + w1.y) * 0.25f,
                         (u1.z + u1.w + w1.z + w1.w) * 0.25f };
            *(float4*)&g_l1[img][(size_t)b * L1HW + (size_t)(OY / 2 + r) * 256
                                 + OX / 2 + 4 * c4] = o;
        }
    }

    // ---- Stage BC (fused): 4 medians/task from 6 LDS.128 + 3 LDS ----
    for (int i = tid; i < 612; i += 256) {         // 2 img x 34 rows x 9 quads
        int img = i / 306;
        int rem = i - img * 306;
        int r   = rem / 9;
        int q   = rem - 9 * r;
        int c0  = 4 * q;
        float f[3][8], e[3];
#pragma unroll
        for (int rr = 0; rr < 3; rr++) {
            *(float4*)&f[rr][0] = *(const float4*)&sm.g[img][r + rr][c0];
            *(float4*)&f[rr][4] = *(const float4*)&sm.g[img][r + rr][c0 + 4];
            e[rr] = sm.g[img][r + rr][c0 + 8];
        }
        float lo[6], mi[6], hi[6];
#pragma unroll
        for (int j = 0; j < 6; j++) {              // triple at gray cc = c0+3+j
            float v0 = (j < 5) ? f[0][3 + j] : e[0];
            float v1 = (j < 5) ? f[1][3 + j] : e[1];
            float v2 = (j < 5) ? f[2][3 + j] : e[2];
            sort3f(v0, v1, v2);
            lo[j] = v0; mi[j] = v1; hi[j] = v2;
        }
        float out[4];
#pragma unroll
        for (int m = 0; m < 4; m++) {
            float L  = fmaxf(fmaxf(lo[m], lo[m + 1]), lo[m + 2]);
            float M  = med3f(mi[m], mi[m + 1], mi[m + 2]);
            float Hh = fminf(fminf(hi[m], hi[m + 1]), hi[m + 2]);
            out[m] = med3f(L, M, Hh);
        }
        *(float4*)&sm.med[img][r][c0] = *(float4*)&out[0];
    }
    __syncthreads();

    // ---- Stage D: Prewitt + GMS, 4 px/thread via 12 LDS.128 ----
    const float C9 = 9.0f * C_GMS;
    const int q   = tid & 7;
    const int row = tid >> 3;
    float t[2][4];
#pragma unroll
    for (int img = 0; img < 2; img++) {
        float r0[8], r1[8], r2[8];
        *(float4*)&r0[0] = *(const float4*)&sm.med[img][row][4 * q];
        *(float4*)&r0[4] = *(const float4*)&sm.med[img][row][4 * q + 4];
        *(float4*)&r1[0] = *(const float4*)&sm.med[img][row + 1][4 * q];
        *(float4*)&r1[4] = *(const float4*)&sm.med[img][row + 1][4 * q + 4];
        *(float4*)&r2[0] = *(const float4*)&sm.med[img][row + 2][4 * q];
        *(float4*)&r2[4] = *(const float4*)&sm.med[img][row + 2][4 * q + 4];
        float cs[6];
#pragma unroll
        for (int c = 0; c < 6; c++) cs[c] = r0[c] + r1[c] + r2[c];
#pragma unroll
        for (int j = 0; j < 4; j++) {
            float u = cs[j + 2] - cs[j];
            float v = (r0[j] + r0[j + 1] + r0[j + 2]) - (r2[j] + r2[j + 1] + r2[j + 2]);
            t[img][j] = u * u + v * v;
        }
    }
    float acc = 0.0f;
#pragma unroll
    for (int j = 0; j < 4; j++) {
        bool valid = interior || ((OY + row < H - 2) && (OX + 4 * q + j < W - 2));
        if (valid) {
            float p = t[0][j] * t[1][j];
            float s = p * rsqrtf(p + 1e-30f);      // sqrt(p), branchless, 0-safe
            float num = 2.0f * s + C9;
            float den = t[0][j] + t[1][j] + C9;
            acc += 1.0f - __fdividef(num, den);
        }
    }

    // ---- block reduction ----
#pragma unroll
    for (int o = 16; o > 0; o >>= 1) acc += __shfl_down_sync(0xffffffffu, acc, o);
    if ((tid & 31) == 0) sm.wsum[tid >> 5] = acc;
    __syncthreads();
    if (tid < 8) {
        float s = sm.wsum[tid];
#pragma unroll
        for (int o = 4; o > 0; o >>= 1) s += __shfl_down_sync(0xffu, s, o);
        if (tid == 0) {
            constexpr float wgt = 1.0f / (4.0f * (float)NB * (float)(H - 2) * (float)(W - 2));
            g_partial[gbid] = (double)(s * wgt);
        }
    }
}

__global__ __launch_bounds__(256) void gms0_k(const float* __restrict__ Ii,
                                              const float* __restrict__ Ir) {
    __shared__ Smem sm;
    gms_tile<512, 512, 4, 0>(sm, blockIdx.x, blockIdx.x, Ii, Ir);
}

__global__ __launch_bounds__(256) void gms123_k() {
    __shared__ Smem sm;
    const int bid = blockIdx.x;
    if (bid < N1) {
        gms_tile<256, 256, 3, 1>(sm, bid, N0 + bid, nullptr, nullptr);
    } else if (bid < N1 + N2) {
        gms_tile<128, 128, 2, 2>(sm, bid - N1, N0 + bid, nullptr, nullptr);
    } else {
        gms_tile<64, 64, 1, 4>(sm, bid - N1 - N2, N0 + bid, nullptr, nullptr);
    }
}

// ---------------------------------------------------------------------------
// Deterministic fixed-order reduction of per-block partials.
// ---------------------------------------------------------------------------
__global__ __launch_bounds__(256) void finalize_k(float* __restrict__ out) {
    __shared__ double ws[8];
    double s = 0.0;
    for (int i = threadIdx.x; i < NBLK; i += 256) s += g_partial[i];
#pragma unroll
    for (int o = 16; o > 0; o >>= 1) s += __shfl_down_sync(0xffffffffu, s, o);
    if ((threadIdx.x & 31) == 0) ws[threadIdx.x >> 5] = s;
    __syncthreads();
    if (threadIdx.x < 8) {
        double t = ws[threadIdx.x];
#pragma unroll
        for (int o = 4; o > 0; o >>= 1) t += __shfl_down_sync(0xffu, t, o);
        if (threadIdx.x == 0) out[0] = (float)t;
    }
}

// ---------------------------------------------------------------------------
extern "C" void kernel_launch(void* const* d_in, const int* in_sizes, int n_in,
                              void* d_out, int out_size) {
    const float* Ii = (const float*)d_in[0];
    const float* Ir = (const float*)d_in[1];
    float* out = (float*)d_out;

    gms0_k<<<N0, 256>>>(Ii, Ir);
    gms123_k<<<N123, 256>>>();
    finalize_k<<<1, 256>>>(out);
}

// round 12
// speedup vs baseline: 1.6090x; 1.6090x over previous
#include <cuda_runtime.h>

// ---------------------------------------------------------------------------
// MSGMS loss, 4-scale pyramid.
//  Kernel 1 (graypyr_k): fused grayscale + avg-pool pyramid (~65% DRAM, at floor).
//  Kernel 2 (gms_all_k): ALL 4 scales, one launch, 64x32 tiles, 512 threads.
//     stage A : gray tile (68x48) via unified per-quad loads
//     stage BC: fused vertical sort3 + horizontal median-of-9 combine
//     stage D : Prewitt + gmap via MUFU intrinsics; 4 px/thread
//     -> per-block partial in g_partial[bid]
//  Kernel 3 (finalize_k): fixed-order deterministic sum.
// ---------------------------------------------------------------------------

#define C_GMS 0.0026f

static constexpr int NB   = 16;
static constexpr int HW0  = 512 * 512;
static constexpr int OFF0 = 0;
static constexpr int OFF1 = OFF0 + 16 * 512 * 512;
static constexpr int OFF2 = OFF1 + 16 * 256 * 256;
static constexpr int OFF3 = OFF2 + 16 * 128 * 128;
static constexpr int GTOT = OFF3 + 16 * 64 * 64;

// 64-row x 32-col tiles
static constexpr int N0 = 16 * 8 * NB;    // 2048 tiles @512
static constexpr int N1 = 8 * 4 * NB;     // 512  @256
static constexpr int N2 = 4 * 2 * NB;     // 128  @128
static constexpr int N3 = 2 * 1 * NB;     // 32   @64
static constexpr int NBLK = N0 + N1 + N2 + N3;  // 2720

__device__ float  g_gray[2][GTOT];
__device__ double g_partial[NBLK];

// ---------------------------------------------------------------------------
// Kernel 1: grayscale + pooled pyramid (register-fused gray->L1, 10KB smem).
// ---------------------------------------------------------------------------
__global__ __launch_bounds__(256) void graypyr_k(const float* __restrict__ Ii,
                                                 const float* __restrict__ Ir) {
    const int s = blockIdx.x;   // stripe 0..63 (L0 rows 8s..8s+7)
    const int b = blockIdx.y;   // batch
    const int tid = threadIdx.x;
    __shared__ float s1[2][4][256];
    __shared__ float s2[2][2][128];
    const float inv3 = 1.0f / 3.0f;

    for (int i = tid; i < 1024; i += 256) {
        int img = i >> 9;
        int rem = i & 511;
        int r1  = rem >> 7;      // L1 row 0..3
        int k   = rem & 127;     // col-pair (L0 cols 4k..4k+3)
        const float* base = (img ? Ir : Ii) + (size_t)b * 3 * HW0
                            + (size_t)(s * 8 + 2 * r1) * 512 + 4 * k;
        float4 a0 = *(const float4*)base;
        float4 a1 = *(const float4*)(base + HW0);
        float4 a2 = *(const float4*)(base + 2 * HW0);
        float4 g0 = { (a0.x + a1.x + a2.x) * inv3, (a0.y + a1.y + a2.y) * inv3,
                      (a0.z + a1.z + a2.z) * inv3, (a0.w + a1.w + a2.w) * inv3 };
        const float* baseb = base + 512;
        float4 c0 = *(const float4*)baseb;
        float4 c1 = *(const float4*)(baseb + HW0);
        float4 c2 = *(const float4*)(baseb + 2 * HW0);
        float4 g1 = { (c0.x + c1.x + c2.x) * inv3, (c0.y + c1.y + c2.y) * inv3,
                      (c0.z + c1.z + c2.z) * inv3, (c0.w + c1.w + c2.w) * inv3 };
        float* L0 = &g_gray[img][(size_t)b * HW0 + (size_t)(s * 8 + 2 * r1) * 512 + 4 * k];
        *(float4*)L0         = g0;
        *(float4*)(L0 + 512) = g1;
        float2 l1 = { (g0.x + g0.y + g1.x + g1.y) * 0.25f,
                      (g0.z + g0.w + g1.z + g1.w) * 0.25f };
        *(float2*)&s1[img][r1][2 * k] = l1;
        *(float2*)&g_gray[img][OFF1 + (size_t)b * 256 * 256 + (size_t)(s * 4 + r1) * 256 + 2 * k] = l1;
    }
    __syncthreads();

    for (int i = tid; i < 512; i += 256) {
        int img = i >> 8;
        int rem = i & 255;
        int r   = rem >> 7;
        int c   = rem & 127;
        float2 t0 = *(const float2*)&s1[img][2 * r][2 * c];
        float2 t1 = *(const float2*)&s1[img][2 * r + 1][2 * c];
        float v = (t0.x + t0.y + t1.x + t1.y) * 0.25f;
        s2[img][r][c] = v;
        g_gray[img][OFF2 + (size_t)b * 128 * 128 + (size_t)(s * 2 + r) * 128 + c] = v;
    }
    __syncthreads();

    if (tid < 128) {
        int img = tid >> 6;
        int c   = tid & 63;
        float2 t0 = *(const float2*)&s2[img][0][2 * c];
        float2 t1 = *(const float2*)&s2[img][1][2 * c];
        float v = (t0.x + t0.y + t1.x + t1.y) * 0.25f;
        g_gray[img][OFF3 + (size_t)b * 64 * 64 + (size_t)s * 64 + c] = v;
    }
}

// ---------------------------------------------------------------------------
// Fused GMS tile: 64 rows x 32 cols output, 512 threads.
// gray stride 48 (col cc = OX-4+cc), med stride 40; quads 16B-aligned.
// ---------------------------------------------------------------------------
struct Smem {
    float g[2][68][48];     // gray: row r = gray row OY-1+r
    float med[2][66][40];   // median-of-9 tile
    float wsum[16];
};

__device__ __forceinline__ float med3f(float a, float b, float c) {
    return fmaxf(fminf(a, b), fminf(fmaxf(a, b), c));
}
__device__ __forceinline__ void sort3f(float& a, float& b, float& c) {
    float t;
    t = fminf(a, b); b = fmaxf(a, b); a = t;
    t = fminf(b, c); c = fmaxf(b, c); b = t;
    t = fminf(a, b); b = fmaxf(a, b); a = t;
}

template <int H, int W, int LOGTX>
__device__ __forceinline__ void gms_tile(Smem& sm, int local, int off, int gbid) {
    constexpr int TX = 1 << LOGTX;            // col tiles (W/32)
    constexpr int TY = TX / 2;                // row tiles (H/64), >=1
    constexpr int LOGTY = (LOGTX > 0) ? (LOGTX - 1) : 0;
    const int bx = local & (TX - 1);
    const int by = (local >> LOGTX) & (TY - 1);
    const int b  = local >> (LOGTX + LOGTY);
    const int OX = bx * 32;
    const int OY = by * 64;
    const int tid = threadIdx.x;

    const float* __restrict__ g0 = &g_gray[0][off + (size_t)b * H * W];
    const float* __restrict__ g1 = &g_gray[1][off + (size_t)b * H * W];

    const bool interior = (OX >= 4) && (OX + 36 <= W) && (OY >= 1) && (OY + 67 <= H);

    // ---- Stage A: gray tile (2 img x 68 rows x 12 quads = 1632 tasks) ----
    for (int i = tid; i < 1632; i += 512) {
        int img = (i >= 816);
        int rem = i - img * 816;
        int r   = rem / 12;
        int k   = rem - 12 * r;
        int gy  = OY - 1 + r;
        int gc  = OX - 4 + 4 * k;
        const float* g = img ? g1 : g0;
        float vv[4] = {0.f, 0.f, 0.f, 0.f};
        if ((unsigned)gy < (unsigned)H) {
            if (gc >= 0 && gc + 4 <= W) {
                *(float4*)vv = *(const float4*)(g + (size_t)gy * W + gc);
            } else {
#pragma unroll
                for (int j = 0; j < 4; j++) {
                    int x = gc + j;
                    if ((unsigned)x < (unsigned)W)
                        vv[j] = __ldg(g + (size_t)gy * W + x);
                }
            }
        }
        *(float4*)&sm.g[img][r][4 * k] = *(float4*)vv;
    }
    __syncthreads();

    // ---- Stage BC (fused): 4 medians/task (2 img x 66 rows x 9 quads = 1188) ----
    for (int i = tid; i < 1188; i += 512) {
        int img = (i >= 594);
        int rem = i - img * 594;
        int r   = rem / 9;
        int q   = rem - 9 * r;
        int c0  = 4 * q;
        float f[3][8], e[3];
#pragma unroll
        for (int rr = 0; rr < 3; rr++) {
            *(float4*)&f[rr][0] = *(const float4*)&sm.g[img][r + rr][c0];
            *(float4*)&f[rr][4] = *(const float4*)&sm.g[img][r + rr][c0 + 4];
            e[rr] = sm.g[img][r + rr][c0 + 8];
        }
        float lo[6], mi[6], hi[6];
#pragma unroll
        for (int j = 0; j < 6; j++) {              // triple at gray cc = c0+3+j
            float v0 = (j < 5) ? f[0][3 + j] : e[0];
            float v1 = (j < 5) ? f[1][3 + j] : e[1];
            float v2 = (j < 5) ? f[2][3 + j] : e[2];
            sort3f(v0, v1, v2);
            lo[j] = v0; mi[j] = v1; hi[j] = v2;
        }
        float out[4];
#pragma unroll
        for (int m = 0; m < 4; m++) {
            float L  = fmaxf(fmaxf(lo[m], lo[m + 1]), lo[m + 2]);
            float M  = med3f(mi[m], mi[m + 1], mi[m + 2]);
            float Hh = fminf(fminf(hi[m], hi[m + 1]), hi[m + 2]);
            out[m] = med3f(L, M, Hh);
        }
        *(float4*)&sm.med[img][r][c0] = *(float4*)&out[0];
    }
    __syncthreads();

    // ---- Stage D: Prewitt + GMS, 4 px/thread via 12 LDS.128 ----
    const float C9 = 9.0f * C_GMS;
    const int q   = tid & 7;          // col quad: output cols OX+4q..OX+4q+3
    const int row = tid >> 3;         // output row OY+row, 0..63
    float t[2][4];
#pragma unroll
    for (int img = 0; img < 2; img++) {
        float r0[8], r1[8], r2[8];
        *(float4*)&r0[0] = *(const float4*)&sm.med[img][row][4 * q];
        *(float4*)&r0[4] = *(const float4*)&sm.med[img][row][4 * q + 4];
        *(float4*)&r1[0] = *(const float4*)&sm.med[img][row + 1][4 * q];
        *(float4*)&r1[4] = *(const float4*)&sm.med[img][row + 1][4 * q + 4];
        *(float4*)&r2[0] = *(const float4*)&sm.med[img][row + 2][4 * q];
        *(float4*)&r2[4] = *(const float4*)&sm.med[img][row + 2][4 * q + 4];
        float cs[6];
#pragma unroll
        for (int c = 0; c < 6; c++) cs[c] = r0[c] + r1[c] + r2[c];
#pragma unroll
        for (int j = 0; j < 4; j++) {
            float u = cs[j + 2] - cs[j];
            float v = (r0[j] + r0[j + 1] + r0[j + 2]) - (r2[j] + r2[j + 1] + r2[j + 2]);
            t[img][j] = u * u + v * v;
        }
    }
    float acc = 0.0f;
#pragma unroll
    for (int j = 0; j < 4; j++) {
        bool valid = interior || ((OY + row < H - 2) && (OX + 4 * q + j < W - 2));
        if (valid) {
            float p = t[0][j] * t[1][j];
            float s = p * rsqrtf(p + 1e-30f);      // sqrt(p), branchless, 0-safe
            float num = 2.0f * s + C9;
            float den = t[0][j] + t[1][j] + C9;
            acc += 1.0f - __fdividef(num, den);
        }
    }

    // ---- block reduction (16 warps) ----
#pragma unroll
    for (int o = 16; o > 0; o >>= 1) acc += __shfl_down_sync(0xffffffffu, acc, o);
    if ((tid & 31) == 0) sm.wsum[tid >> 5] = acc;
    __syncthreads();
    if (tid < 16) {
        float s = sm.wsum[tid];
#pragma unroll
        for (int o = 8; o > 0; o >>= 1) s += __shfl_down_sync(0xffffu, s, o);
        if (tid == 0) {
            constexpr float wgt = 1.0f / (4.0f * (float)NB * (float)(H - 2) * (float)(W - 2));
            g_partial[gbid] = (double)(s * wgt);
        }
    }
}

__global__ __launch_bounds__(512) void gms_all_k() {
    __shared__ Smem sm;
    const int bid = blockIdx.x;
    if (bid < N0) {
        gms_tile<512, 512, 4>(sm, bid, OFF0, bid);
    } else if (bid < N0 + N1) {
        gms_tile<256, 256, 3>(sm, bid - N0, OFF1, bid);
    } else if (bid < N0 + N1 + N2) {
        gms_tile<128, 128, 2>(sm, bid - N0 - N1, OFF2, bid);
    } else {
        gms_tile<64, 64, 1>(sm, bid - N0 - N1 - N2, OFF3, bid);
    }
}

// ---------------------------------------------------------------------------
// Kernel 3: deterministic fixed-order reduction of per-block partials.
// ---------------------------------------------------------------------------
__global__ __launch_bounds__(256) void finalize_k(float* __restrict__ out) {
    __shared__ double ws[8];
    double s = 0.0;
    for (int i = threadIdx.x; i < NBLK; i += 256) s += g_partial[i];
#pragma unroll
    for (int o = 16; o > 0; o >>= 1) s += __shfl_down_sync(0xffffffffu, s, o);
    if ((threadIdx.x & 31) == 0) ws[threadIdx.x >> 5] = s;
    __syncthreads();
    if (threadIdx.x < 8) {
        double t = ws[threadIdx.x];
#pragma unroll
        for (int o = 4; o > 0; o >>= 1) t += __shfl_down_sync(0xffu, t, o);
        if (threadIdx.x == 0) out[0] = (float)t;
    }
}

// ---------------------------------------------------------------------------
extern "C" void kernel_launch(void* const* d_in, const int* in_sizes, int n_in,
                              void* d_out, int out_size) {
    const float* Ii = (const float*)d_in[0];
    const float* Ir = (const float*)d_in[1];
    float* out = (float*)d_out;

    graypyr_k<<<dim3(64, NB), 256>>>(Ii, Ir);
    gms_all_k<<<NBLK, 512>>>();
    finalize_k<<<1, 256>>>(out);
}